// round 2
// baseline (speedup 1.0000x reference)
#include <cuda_runtime.h>

#define BB 8192
#define CC 1024
#define SS 16

// ---- scratch (static device globals; no runtime allocation) ----
__device__ float g_psum[256];
__device__ float g_psumsq[256];
__device__ float g_scale;      // 1 / (std_ddof1 * temperature)
__device__ float g_tv[SS];     // ndtri((k+0.5)/16)
__device__ float g_probs[BB];

// ---------------- stage 1: partial sums over all logits ----------------
__global__ void __launch_bounds__(256) stats1_kernel(const float* __restrict__ x) {
    int tid = blockIdx.x * 256 + threadIdx.x;            // 0..65535
    const float4* x4 = (const float4*)x;
    float s = 0.f, ss = 0.f;
    const int n4 = (BB * CC) / 4;                        // 2097152
    for (int i = tid; i < n4; i += 65536) {
        float4 v = x4[i];
        s  += v.x + v.y + v.z + v.w;
        ss += v.x * v.x + v.y * v.y + v.z * v.z + v.w * v.w;
    }
    __shared__ float sh[256], sh2[256];
    sh[threadIdx.x] = s; sh2[threadIdx.x] = ss;
    __syncthreads();
    for (int o = 128; o > 0; o >>= 1) {
        if (threadIdx.x < o) { sh[threadIdx.x] += sh[threadIdx.x + o]; sh2[threadIdx.x] += sh2[threadIdx.x + o]; }
        __syncthreads();
    }
    if (threadIdx.x == 0) { g_psum[blockIdx.x] = sh[0]; g_psumsq[blockIdx.x] = sh2[0]; }
}

// ---------------- stage 2: finalize scale + quadrature nodes ----------------
__global__ void stats2_kernel(const float* __restrict__ temperature) {
    __shared__ double sh[256], sh2[256];
    int t = threadIdx.x;
    sh[t]  = (double)g_psum[t];
    sh2[t] = (double)g_psumsq[t];
    __syncthreads();
    for (int o = 128; o > 0; o >>= 1) {
        if (t < o) { sh[t] += sh[t + o]; sh2[t] += sh2[t + o]; }
        __syncthreads();
    }
    if (t < SS) {
        g_tv[t] = (float)normcdfinv(((double)t + 0.5) / (double)SS);
    }
    if (t == 0) {
        double n    = (double)BB * (double)CC;
        double var  = (sh2[0] - sh[0] * sh[0] / n) / (n - 1.0);  // ddof=1
        g_scale = (float)(1.0 / (sqrt(var) * (double)temperature[0]));
    }
}

// ---------------- fast standard-normal CDF (A&S 7.1.26) ----------------
// abs error ~1e-7 in Phi; product formulation means no log needed.
__device__ __forceinline__ float ncdf(float x) {
    float z = fabsf(x) * 0.70710678118654752f;
    float t = __fdividef(1.0f, fmaf(0.3275911f, z, 1.0f));
    float poly = t * fmaf(t, fmaf(t, fmaf(t, fmaf(t, 1.061405429f, -1.453152027f),
                                          1.421413741f), -0.284496736f), 0.254829592f);
    float q = 0.5f * poly * __expf(-z * z);
    return (x >= 0.f) ? 1.0f - q : q;
}

// ---------------- main: one block per batch row ----------------
__global__ void __launch_bounds__(256) exact_main_kernel(const float* __restrict__ logits,
                                                         const int* __restrict__ labels) {
    __shared__ float ds[CC];     // delta row (target minus each logit, scaled)
    __shared__ float pk[SS];     // per-quadrature-node products
    const int b   = blockIdx.x;
    const int tid = threadIdx.x;
    const float* row = logits + (size_t)b * CC;
    const int   y     = labels[b];
    const float scale = g_scale;
    const float tgt   = __ldg(row + y);

    // build delta row in smem; sentinel +30 at target column -> factor exactly 1.0
    {
        float4 v = ((const float4*)row)[tid];
        int base = tid * 4;
        float4 d;
        d.x = (base + 0 == y) ? 30.0f : (tgt - v.x) * scale;
        d.y = (base + 1 == y) ? 30.0f : (tgt - v.y) * scale;
        d.z = (base + 2 == y) ? 30.0f : (tgt - v.z) * scale;
        d.w = (base + 3 == y) ? 30.0f : (tgt - v.w) * scale;
        ((float4*)ds)[tid] = d;
    }
    __syncthreads();

    // each warp owns two quadrature nodes; lanes stride the class dim in float4s.
    // 8 independent product chains (2 nodes x 4 components) hide MUFU latency.
    const int w = tid >> 5, lane = tid & 31;
    const float t0 = g_tv[2 * w];
    const float t1 = g_tv[2 * w + 1];
    const float4* ds4 = (const float4*)ds;

    float a0 = 1.0f, a1 = 1.0f, a2 = 1.0f, a3 = 1.0f;   // node t0 chains
    float b0 = 1.0f, b1 = 1.0f, b2 = 1.0f, b3 = 1.0f;   // node t1 chains
    #pragma unroll
    for (int i = 0; i < CC / 4 / 32; i++) {              // 8 iterations
        float4 d = ds4[lane + 32 * i];
        a0 *= ncdf(d.x + t0);  b0 *= ncdf(d.x + t1);
        a1 *= ncdf(d.y + t0);  b1 *= ncdf(d.y + t1);
        a2 *= ncdf(d.z + t0);  b2 *= ncdf(d.z + t1);
        a3 *= ncdf(d.w + t0);  b3 *= ncdf(d.w + t1);
    }
    float p0 = (a0 * a1) * (a2 * a3);
    float p1 = (b0 * b1) * (b2 * b3);

    // warp product reduction
    #pragma unroll
    for (int o = 16; o > 0; o >>= 1) {
        p0 *= __shfl_xor_sync(0xffffffffu, p0, o);
        p1 *= __shfl_xor_sync(0xffffffffu, p1, o);
    }
    if (lane == 0) { pk[2 * w] = p0; pk[2 * w + 1] = p1; }
    __syncthreads();

    if (tid == 0) {
        float s = 0.f;
        #pragma unroll
        for (int k = 0; k < SS; k++) s += pk[k];
        g_probs[b] = s * (1.0f / SS);
    }
}

// ---------------- final: loss = 1 - mean(probs) ----------------
__global__ void __launch_bounds__(1024) final_kernel(float* __restrict__ out) {
    __shared__ float sh[1024];
    int t = threadIdx.x;
    float s = 0.f;
    for (int i = t; i < BB; i += 1024) s += g_probs[i];
    sh[t] = s;
    __syncthreads();
    for (int o = 512; o > 0; o >>= 1) {
        if (t < o) sh[t] += sh[t + o];
        __syncthreads();
    }
    if (t == 0) out[0] = 1.0f - sh[0] * (1.0f / (float)BB);
}

// ---------------- launcher ----------------
extern "C" void kernel_launch(void* const* d_in, const int* in_sizes, int n_in,
                              void* d_out, int out_size) {
    const float* logits      = (const float*)d_in[0];
    const int*   labels      = (const int*)d_in[1];
    const float* temperature = (const float*)d_in[2];
    (void)in_sizes; (void)n_in; (void)out_size;

    stats1_kernel<<<256, 256>>>(logits);
    stats2_kernel<<<1, 256>>>(temperature);
    exact_main_kernel<<<BB, 256>>>(logits, labels);
    final_kernel<<<1, 1024>>>((float*)d_out);
}

// round 6
// speedup vs baseline: 1.7182x; 1.7182x over previous
#include <cuda_runtime.h>

#define BB 8192
#define CC 1024
#define SS 16

// ---- scratch (static device globals; no runtime allocation) ----
__device__ float g_psum[256];
__device__ float g_psumsq[256];
__device__ float g_scale;          // 1 / (std_ddof1 * temperature)
__device__ float g_tv[SS];         // ndtri((k+0.5)/16)
__device__ float g_probs[BB];
__device__ unsigned int g_cnt;     // last-block-done counter (reset by stats2)

// ---------------- stage 1: partial sums over all logits ----------------
__global__ void __launch_bounds__(256) stats1_kernel(const float* __restrict__ x) {
    int tid = blockIdx.x * 256 + threadIdx.x;            // 0..65535
    const float4* x4 = (const float4*)x;
    float s = 0.f, ss = 0.f;
    const int n4 = (BB * CC) / 4;                        // 2097152
    for (int i = tid; i < n4; i += 65536) {
        float4 v = x4[i];
        s  += v.x + v.y + v.z + v.w;
        ss += v.x * v.x + v.y * v.y + v.z * v.z + v.w * v.w;
    }
    __shared__ float sh[256], sh2[256];
    sh[threadIdx.x] = s; sh2[threadIdx.x] = ss;
    __syncthreads();
    for (int o = 128; o > 0; o >>= 1) {
        if (threadIdx.x < o) { sh[threadIdx.x] += sh[threadIdx.x + o]; sh2[threadIdx.x] += sh2[threadIdx.x + o]; }
        __syncthreads();
    }
    if (threadIdx.x == 0) { g_psum[blockIdx.x] = sh[0]; g_psumsq[blockIdx.x] = sh2[0]; }
}

// ---------------- stage 2: finalize scale + quadrature nodes + counter reset ----------------
__global__ void stats2_kernel(const float* __restrict__ temperature) {
    __shared__ double sh[256], sh2[256];
    int t = threadIdx.x;
    sh[t]  = (double)g_psum[t];
    sh2[t] = (double)g_psumsq[t];
    __syncthreads();
    for (int o = 128; o > 0; o >>= 1) {
        if (t < o) { sh[t] += sh[t + o]; sh2[t] += sh2[t + o]; }
        __syncthreads();
    }
    if (t < SS) {
        g_tv[t] = (float)normcdfinv(((double)t + 0.5) / (double)SS);
    }
    if (t == 0) {
        double n    = (double)BB * (double)CC;
        double var  = (sh2[0] - sh[0] * sh[0] / n) / (n - 1.0);  // ddof=1
        g_scale = (float)(1.0 / (sqrt(var) * (double)temperature[0]));
        g_cnt = 0u;   // reset last-block counter for the main kernel
    }
}

// ---------------- fast standard-normal CDF via MUFU.TANH ----------------
// Phi(x) ~= 0.5 + 0.5*tanh(x*(c1 + c3 x^2 + c5 x^4)); fitted, |err| <~ 1e-4
// plus tanh.approx HW error (<~2.5e-4 in Phi). Clamp keeps the quintic
// argument monotone-positive (it would go wrong past |x|~11).
__device__ __forceinline__ float phi_tanh(float s) {
    s = fminf(fmaxf(s, -6.0f), 6.0f);
    float s2 = s * s;
    float h  = fmaf(s2, fmaf(s2, -0.000361223f, 0.0368965f), 0.798241f);
    float y  = s * h;
    float th;
    asm("tanh.approx.f32 %0, %1;" : "=f"(th) : "f"(y));
    return fmaf(0.5f, th, 0.5f);
}

// ---------------- main: one block per batch row (+ fused final reduce) ----------------
__global__ void __launch_bounds__(256) exact_main_kernel(const float* __restrict__ logits,
                                                         const int* __restrict__ labels,
                                                         float* __restrict__ out) {
    __shared__ float ds[CC];     // delta row (target minus each logit, scaled)
    __shared__ float pk[SS];     // per-quadrature-node products
    __shared__ bool  s_last;
    const int b   = blockIdx.x;
    const int tid = threadIdx.x;
    const float* row = logits + (size_t)b * CC;
    const int   y     = labels[b];
    const float scale = g_scale;
    const float tgt   = __ldg(row + y);

    // build delta row in smem; sentinel +30 at target column -> clamps to 6 -> factor ~1.0
    {
        float4 v = ((const float4*)row)[tid];
        int base = tid * 4;
        float4 d;
        d.x = (base + 0 == y) ? 30.0f : (tgt - v.x) * scale;
        d.y = (base + 1 == y) ? 30.0f : (tgt - v.y) * scale;
        d.z = (base + 2 == y) ? 30.0f : (tgt - v.z) * scale;
        d.w = (base + 3 == y) ? 30.0f : (tgt - v.w) * scale;
        ((float4*)ds)[tid] = d;
    }
    __syncthreads();

    // each warp owns two quadrature nodes; lanes stride the class dim in float4s.
    // 8 independent product chains (2 nodes x 4 components) hide MUFU latency.
    const int w = tid >> 5, lane = tid & 31;
    const float t0 = g_tv[2 * w];
    const float t1 = g_tv[2 * w + 1];
    const float4* ds4 = (const float4*)ds;

    float a0 = 1.0f, a1 = 1.0f, a2 = 1.0f, a3 = 1.0f;   // node t0 chains
    float b0 = 1.0f, b1 = 1.0f, b2 = 1.0f, b3 = 1.0f;   // node t1 chains
    #pragma unroll
    for (int i = 0; i < CC / 4 / 32; i++) {              // 8 iterations
        float4 d = ds4[lane + 32 * i];
        a0 *= phi_tanh(d.x + t0);  b0 *= phi_tanh(d.x + t1);
        a1 *= phi_tanh(d.y + t0);  b1 *= phi_tanh(d.y + t1);
        a2 *= phi_tanh(d.z + t0);  b2 *= phi_tanh(d.z + t1);
        a3 *= phi_tanh(d.w + t0);  b3 *= phi_tanh(d.w + t1);
    }
    float p0 = (a0 * a1) * (a2 * a3);
    float p1 = (b0 * b1) * (b2 * b3);

    // warp product reduction
    #pragma unroll
    for (int o = 16; o > 0; o >>= 1) {
        p0 *= __shfl_xor_sync(0xffffffffu, p0, o);
        p1 *= __shfl_xor_sync(0xffffffffu, p1, o);
    }
    if (lane == 0) { pk[2 * w] = p0; pk[2 * w + 1] = p1; }
    __syncthreads();

    if (tid == 0) {
        float s = 0.f;
        #pragma unroll
        for (int k = 0; k < SS; k++) s += pk[k];
        g_probs[b] = s * (1.0f / SS);
        __threadfence();
        unsigned int done = atomicAdd(&g_cnt, 1u);
        s_last = (done == BB - 1u);
    }
    __syncthreads();

    // last finishing block computes loss = 1 - mean(probs), deterministically
    if (s_last) {
        __shared__ float sh[256];
        float s = 0.f;
        #pragma unroll
        for (int i = 0; i < BB / 256; i++) s += g_probs[tid + 256 * i];
        sh[tid] = s;
        __syncthreads();
        for (int o = 128; o > 0; o >>= 1) {
            if (tid < o) sh[tid] += sh[tid + o];
            __syncthreads();
        }
        if (tid == 0) out[0] = 1.0f - sh[0] * (1.0f / (float)BB);
    }
}

// ---------------- launcher ----------------
extern "C" void kernel_launch(void* const* d_in, const int* in_sizes, int n_in,
                              void* d_out, int out_size) {
    const float* logits      = (const float*)d_in[0];
    const int*   labels      = (const int*)d_in[1];
    const float* temperature = (const float*)d_in[2];
    (void)in_sizes; (void)n_in; (void)out_size;

    stats1_kernel<<<256, 256>>>(logits);
    stats2_kernel<<<1, 256>>>(temperature);
    exact_main_kernel<<<BB, 256>>>(logits, labels, (float*)d_out);
}

// round 12
// speedup vs baseline: 1.8786x; 1.0934x over previous
#include <cuda_runtime.h>

#define BB 8192
#define CC 1024
#define SS 16
#define S1GRID 1024

// ---- scratch (static device globals; no runtime allocation) ----
__device__ float g_psum[S1GRID];
__device__ float g_psumsq[S1GRID];
__device__ float g_scale;          // 1 / (std_ddof1 * temperature)
__device__ float g_tv[SS];         // ndtri((k+0.5)/16)
__device__ float g_probs[BB];
__device__ unsigned int g_cnt1 = 0u;   // stats1 last-block counter
__device__ unsigned int g_cnt2 = 0u;   // main   last-block counter

// ---------------- stage 1: global sum/sumsq + fused finalize ----------------
__global__ void __launch_bounds__(256) stats1_kernel(const float* __restrict__ x,
                                                     const float* __restrict__ temperature) {
    const int tid = blockIdx.x * 256 + threadIdx.x;
    const float4* x4 = (const float4*)x;
    float s = 0.f, ss = 0.f;
    const int n4 = (BB * CC) / 4;                        // 2097152
    #pragma unroll
    for (int k = 0; k < n4 / (S1GRID * 256); k++) {      // 8 independent loads in flight
        float4 v = x4[tid + k * (S1GRID * 256)];
        s  += v.x + v.y + v.z + v.w;
        ss += v.x * v.x + v.y * v.y + v.z * v.z + v.w * v.w;
    }
    __shared__ float sh[256], sh2[256];
    sh[threadIdx.x] = s; sh2[threadIdx.x] = ss;
    __syncthreads();
    for (int o = 128; o > 0; o >>= 1) {
        if (threadIdx.x < o) { sh[threadIdx.x] += sh[threadIdx.x + o]; sh2[threadIdx.x] += sh2[threadIdx.x + o]; }
        __syncthreads();
    }
    __shared__ bool s_last;
    if (threadIdx.x == 0) {
        g_psum[blockIdx.x] = sh[0]; g_psumsq[blockIdx.x] = sh2[0];
        __threadfence();
        unsigned int done = atomicAdd(&g_cnt1, 1u);
        s_last = (done == S1GRID - 1u);
    }
    __syncthreads();

    if (s_last) {  // finalize: scale + quadrature nodes + counter resets
        __shared__ double dsum[256], dsq[256];
        const int t = threadIdx.x;
        double a = 0.0, b = 0.0;
        #pragma unroll
        for (int k = 0; k < S1GRID / 256; k++) {
            a += (double)g_psum[t + 256 * k];
            b += (double)g_psumsq[t + 256 * k];
        }
        dsum[t] = a; dsq[t] = b;
        __syncthreads();
        for (int o = 128; o > 0; o >>= 1) {
            if (t < o) { dsum[t] += dsum[t + o]; dsq[t] += dsq[t + o]; }
            __syncthreads();
        }
        if (t < SS) g_tv[t] = (float)normcdfinv(((double)t + 0.5) / (double)SS);
        if (t == 0) {
            double n   = (double)BB * (double)CC;
            double var = (dsq[0] - dsum[0] * dsum[0] / n) / (n - 1.0);  // ddof=1
            g_scale = (float)(1.0 / (sqrt(var) * (double)temperature[0]));
            g_cnt1 = 0u;   // reset for next graph replay
        }
    }
}

// ---------------- fast standard-normal CDF via MUFU.TANH ----------------
// Phi(x) ~= 0.5 + 0.5*tanh(x*(c1 + c3 x^2 + c5 x^4)); |err| <~ 1e-4 + HW tanh err.
// Caller guarantees |s| <= 9.87 (deltas pre-clamped to +-8, |t| <= 1.864), which
// keeps the quintic argument correct-signed (it would misbehave past |s|~11).
__device__ __forceinline__ float phi_tanh(float s) {
    float s2 = s * s;
    float h  = fmaf(s2, fmaf(s2, -0.000361223f, 0.0368965f), 0.798241f);
    float y  = s * h;
    float th;
    asm("tanh.approx.f32 %0, %1;" : "=f"(th) : "f"(y));
    return fmaf(0.5f, th, 0.5f);
}

// ---------------- main: one block per batch row (+ fused final reduce) ----------------
__global__ void __launch_bounds__(256) exact_main_kernel(const float* __restrict__ logits,
                                                         const int* __restrict__ labels,
                                                         float* __restrict__ out) {
    __shared__ float ds[CC];     // delta row, pre-clamped to [-8, 8]
    __shared__ float pk[SS];     // per-quadrature-node products
    __shared__ bool  s_last;
    const int b   = blockIdx.x;
    const int tid = threadIdx.x;
    const float* row = logits + (size_t)b * CC;
    const int   y     = labels[b];
    const float scale = g_scale;
    const float tgt   = __ldg(row + y);

    // build clamped delta row in smem; sentinel 8.0 at target -> factor ~1.0
    {
        float4 v = ((const float4*)row)[tid];
        int base = tid * 4;
        float4 d;
        d.x = (base + 0 == y) ? 8.0f : fminf(fmaxf((tgt - v.x) * scale, -8.0f), 8.0f);
        d.y = (base + 1 == y) ? 8.0f : fminf(fmaxf((tgt - v.y) * scale, -8.0f), 8.0f);
        d.z = (base + 2 == y) ? 8.0f : fminf(fmaxf((tgt - v.z) * scale, -8.0f), 8.0f);
        d.w = (base + 3 == y) ? 8.0f : fminf(fmaxf((tgt - v.w) * scale, -8.0f), 8.0f);
        ((float4*)ds)[tid] = d;
    }
    __syncthreads();

    // each warp owns two quadrature nodes; lanes stride the class dim in float4s.
    // 8 independent product chains (2 nodes x 4 components) hide MUFU latency.
    const int w = tid >> 5, lane = tid & 31;
    const float t0 = g_tv[2 * w];
    const float t1 = g_tv[2 * w + 1];
    const float4* ds4 = (const float4*)ds;

    float a0 = 1.0f, a1 = 1.0f, a2 = 1.0f, a3 = 1.0f;   // node t0 chains
    float b0 = 1.0f, b1 = 1.0f, b2 = 1.0f, b3 = 1.0f;   // node t1 chains
    #pragma unroll
    for (int i = 0; i < CC / 4 / 32; i++) {              // 8 iterations
        float4 d = ds4[lane + 32 * i];
        a0 *= phi_tanh(d.x + t0);  b0 *= phi_tanh(d.x + t1);
        a1 *= phi_tanh(d.y + t0);  b1 *= phi_tanh(d.y + t1);
        a2 *= phi_tanh(d.z + t0);  b2 *= phi_tanh(d.z + t1);
        a3 *= phi_tanh(d.w + t0);  b3 *= phi_tanh(d.w + t1);
    }
    float p0 = (a0 * a1) * (a2 * a3);
    float p1 = (b0 * b1) * (b2 * b3);

    // warp product reduction
    #pragma unroll
    for (int o = 16; o > 0; o >>= 1) {
        p0 *= __shfl_xor_sync(0xffffffffu, p0, o);
        p1 *= __shfl_xor_sync(0xffffffffu, p1, o);
    }
    if (lane == 0) { pk[2 * w] = p0; pk[2 * w + 1] = p1; }
    __syncthreads();

    if (tid == 0) {
        float s = 0.f;
        #pragma unroll
        for (int k = 0; k < SS; k++) s += pk[k];
        g_probs[b] = s * (1.0f / SS);
        __threadfence();
        unsigned int done = atomicAdd(&g_cnt2, 1u);
        s_last = (done == BB - 1u);
    }
    __syncthreads();

    // last finishing block computes loss = 1 - mean(probs), deterministically
    if (s_last) {
        __shared__ float sh[256];
        float s = 0.f;
        #pragma unroll
        for (int i = 0; i < BB / 256; i++) s += g_probs[tid + 256 * i];
        sh[tid] = s;
        __syncthreads();
        for (int o = 128; o > 0; o >>= 1) {
            if (tid < o) sh[tid] += sh[tid + o];
            __syncthreads();
        }
        if (tid == 0) { out[0] = 1.0f - sh[0] * (1.0f / (float)BB); g_cnt2 = 0u; }
    }
}

// ---------------- launcher ----------------
extern "C" void kernel_launch(void* const* d_in, const int* in_sizes, int n_in,
                              void* d_out, int out_size) {
    const float* logits      = (const float*)d_in[0];
    const int*   labels      = (const int*)d_in[1];
    const float* temperature = (const float*)d_in[2];
    (void)in_sizes; (void)n_in; (void)out_size;

    stats1_kernel<<<S1GRID, 256>>>(logits, temperature);
    exact_main_kernel<<<BB, 256>>>(logits, labels, (float*)d_out);
}